// round 17
// baseline (speedup 1.0000x reference)
#include <cuda_runtime.h>
#include <cuda_fp16.h>
#include <cstdint>
#include <math.h>

#define B_SZ 1024
#define T_SZ 128
#define H_SZ 256
#define NG   1024            // 4*H
#define KC   512             // combined K (x | h)
#define BH   (B_SZ * H_SZ)
#define NCTA 128

// ---------------------------------------------------------------------------
// Static device scratch (no cudaMalloc anywhere)
// ---------------------------------------------------------------------------
__device__ __align__(16) __half g_xr  [T_SZ * BH];     // relu(x) time-major fp16
__device__ __align__(16) __half g_hs0 [T_SZ * BH];     // layer-0 h outputs fp16
__device__ __align__(16) __half g_h1  [2][BH];         // layer-1 h double buffered
__device__ __align__(16) __half g_zero_h[BH];          // never written -> zero
__device__ __align__(16) __half g_Wp[2][NG * KC];      // fp16 weights [n'][K], n'=4j+g
__device__ __align__(16) float  g_biasP[2][NG];
__device__ unsigned           g_cnt;                   // barrier arrivals
__device__ volatile unsigned  g_gen;                   // barrier generation
__device__ unsigned           g_hs0done[8];            // per-mblk: 8*(t+1) when hs0[t] ready

// ---------------------------------------------------------------------------
// PTX helpers (plain sm_100: cp.async + ldmatrix + mma.sync)
// ---------------------------------------------------------------------------
__device__ __forceinline__ uint32_t smem_u32(const void* p) {
    uint32_t a;
    asm("{ .reg .u64 t; cvta.to.shared.u64 t, %1; cvt.u32.u64 %0, t; }" : "=r"(a) : "l"(p));
    return a;
}
__device__ __forceinline__ void cpasync16(uint32_t s, const void* g) {
    asm volatile("cp.async.cg.shared.global [%0], [%1], 16;" :: "r"(s), "l"(g));
}
#define CP_COMMIT() asm volatile("cp.async.commit_group;" ::: "memory")
#define CP_WAIT1()  asm volatile("cp.async.wait_group 1;" ::: "memory")
#define CP_WAIT0()  asm volatile("cp.async.wait_group 0;" ::: "memory")

#define LDSM4(r0, r1, r2, r3, addr) asm volatile( \
    "ldmatrix.sync.aligned.m8n8.x4.shared.b16 {%0,%1,%2,%3}, [%4];" \
    : "=r"(r0), "=r"(r1), "=r"(r2), "=r"(r3) : "r"(addr))

#define MMA16816(d, a, b) asm volatile( \
    "mma.sync.aligned.m16n8k16.row.col.f32.f16.f16.f32 " \
    "{%0,%1,%2,%3}, {%4,%5,%6,%7}, {%8,%9}, {%0,%1,%2,%3};" \
    : "+f"((d)[0]), "+f"((d)[1]), "+f"((d)[2]), "+f"((d)[3]) \
    : "r"((a)[0]), "r"((a)[1]), "r"((a)[2]), "r"((a)[3]), "r"((b)[0]), "r"((b)[1]))

// ---------------------------------------------------------------------------
// SMEM layout (all dedicated regions, no aliasing) — R15-proven:
//   B resident: 128 n'-rows x 512 K fp16, pitch 1040B  -> 133120
//   A chunks:   2 bufs x (128 rows x 128 K fp16, pitch 272) -> 2 x 34816
//   h stage:    128 rows x 32 fp16, pitch 80B -> 10240
//   bias:       128 floats -> 512
// ---------------------------------------------------------------------------
#define PITCH_A  272
#define PITCH_B  1040
#define PITCH_H  80
#define OFF_BW   0
#define A_TILE_B 34816
#define OFF_A(b) (133120 + (b) * A_TILE_B)
#define OFF_HST  202752
#define OFF_BIAS 212992
#define SMEM_TOTAL 213504

__device__ __forceinline__ float fsigm(float x) {
    x = fminf(fmaxf(x, -30.f), 30.f);
    return __fdividef(1.f, 1.f + __expf(-x));
}
__device__ __forceinline__ float ftanh(float x) {
    x = fminf(fmaxf(x, -15.f), 15.f);
    float e = __expf(2.f * x);
    return (e - 1.f) * __fdividef(1.f, e + 1.f);
}

// ---------------------------------------------------------------------------
// Prep kernels
// ---------------------------------------------------------------------------
__global__ void prep_weights(const float* __restrict__ wih0, const float* __restrict__ whh0,
                             const float* __restrict__ wih1, const float* __restrict__ whh1) {
    int id = blockIdx.x * blockDim.x + threadIdx.x;
    if (id >= 2 * NG * KC) return;
    int layer = id >> 19;
    int rem   = id & ((1 << 19) - 1);
    int np = rem >> 9;
    int k  = rem & 511;
    int j = np >> 2, g = np & 3;
    int n = g * H_SZ + j;
    const float* wih = layer ? wih1 : wih0;
    const float* whh = layer ? whh1 : whh0;
    float w = (k < H_SZ) ? wih[n * H_SZ + k] : whh[n * H_SZ + (k - H_SZ)];
    g_Wp[layer][np * KC + k] = __float2half(w);
}

__global__ void prep_bias(const float* __restrict__ bih0, const float* __restrict__ bhh0,
                          const float* __restrict__ bih1, const float* __restrict__ bhh1) {
    int id = blockIdx.x * blockDim.x + threadIdx.x;
    if (id >= 2 * NG) return;
    if (id < 8) g_hs0done[id] = 0;     // zero producer counters every launch
    int layer = id >> 10;
    int np = id & 1023;
    int j = np >> 2, g = np & 3;
    int n = g * H_SZ + j;
    const float* bi = layer ? bih1 : bih0;
    const float* bh = layer ? bhh1 : bhh0;
    g_biasP[layer][np] = bi[n] + bh[n];
}

// relu + [B,T,H]->[T,B,H] + fp16 convert
__global__ void relu_cvt(const float* __restrict__ x) {
    int id = blockIdx.x * blockDim.x + threadIdx.x;
    if (id >= T_SZ * B_SZ * (H_SZ / 4)) return;
    int t   = id / (B_SZ * (H_SZ / 4));
    int rem = id % (B_SZ * (H_SZ / 4));
    int b   = rem / (H_SZ / 4);
    int e4  = rem % (H_SZ / 4);
    float4 v = *(const float4*)(x + (size_t)b * T_SZ * H_SZ + t * H_SZ + e4 * 4);
    size_t o = (size_t)t * BH + b * H_SZ + e4 * 4;
    g_xr[o]     = __float2half(fmaxf(v.x, 0.f));
    g_xr[o + 1] = __float2half(fmaxf(v.y, 0.f));
    g_xr[o + 2] = __float2half(fmaxf(v.z, 0.f));
    g_xr[o + 3] = __float2half(fmaxf(v.w, 0.f));
}

// ---------------------------------------------------------------------------
// Persistent LSTM (R15 skeleton): grid (8,8,2) = 128 CTAs, 512 threads, all
// co-resident. B weights SMEM-resident; A streamed BK=128 x 2 bufs; c in
// registers; shuffle epilogue; global barrier per wavefront.
// NEW: next wave's chunk 0 prefetched into buf0 BEFORE the barrier arrival
// (L0: x, dependency-free; L1: hs0[t] gated by the acyclic g_hs0done counter).
// ---------------------------------------------------------------------------
__global__ __launch_bounds__(512, 1) void lstm_persistent() {
    extern __shared__ char smem[];
    const uint32_t sb = smem_u32(smem);
    const int tid  = threadIdx.x;
    const int lane = tid & 31;
    const int wid  = tid >> 5;
    const int wm   = wid & 3;        // 4 m-warps (32 rows each)
    const int wn   = wid >> 2;       // 4 n-warps (32 cols each)
    const int layer = blockIdx.z;
    const int n0 = blockIdx.x * 128;
    const int m0 = blockIdx.y * 128;
    const int mblk = blockIdx.y;
    const int j0 = n0 >> 2;
    const __half* WP = g_Wp[layer];

    // ---- one-time: resident B (128 x 512 fp16) + bias into SMEM ----
    for (int i = tid; i < 128 * 64; i += 512) {      // 16B chunks
        int row = i >> 6, c16 = i & 63;
        cpasync16(sb + OFF_BW + row * PITCH_B + c16 * 16,
                  WP + (size_t)(n0 + row) * KC + c16 * 8);
    }
    CP_COMMIT();
    if (tid < 128) ((float*)(smem + OFF_BIAS))[tid] = g_biasP[layer][n0 + tid];
    CP_WAIT0();
    __syncthreads();

    float c_reg[2][4];
    #pragma unroll
    for (int a = 0; a < 2; a++)
        #pragma unroll
        for (int b = 0; b < 4; b++) c_reg[a][b] = 0.f;

    unsigned gen = g_gen;   // all CTAs read before anyone can advance it

    const uint32_t a_lane = (uint32_t)((lane & 15) * PITCH_A + ((lane >> 4) << 4));
    const uint32_t b_lane = (uint32_t)(((lane & 7) + ((lane >> 4) & 1) * 8) * PITCH_B +
                                       ((lane >> 3) & 1) * 16);

    // prefetch chunk0 of step `pt` (x-source, koff 0) into buf0
    auto prefetch0 = [&](int pt) {
        const __half* asrc = (layer == 0) ? (g_xr + (size_t)pt * BH)
                                          : (g_hs0 + (size_t)pt * BH);
        #pragma unroll
        for (int i = 0; i < 4; i++) {
            int idx = tid + i * 512;
            int row = idx >> 4, c16 = idx & 15;
            cpasync16(sb + OFF_A(0) + row * PITCH_A + c16 * 16,
                      asrc + (size_t)(m0 + row) * H_SZ + c16 * 8);
        }
        CP_COMMIT();
    };

    bool have0 = false;
    if (layer == 0) { prefetch0(0); have0 = true; }   // L0 wave-0 chunk0 = x[0]

    #pragma unroll 1
    for (int u = 0; u <= T_SZ; u++) {
        const int t = u - layer;
        if (t >= 0 && t < T_SZ) {
            // operand sources
            const __half *xs, *hs;
            if (layer == 0) {
                xs = g_xr + (size_t)t * BH;
                hs = (t == 0) ? g_zero_h : (g_hs0 + (size_t)(t - 1) * BH);
            } else {
                xs = g_hs0 + (size_t)t * BH;
                hs = (t == 0) ? g_zero_h : g_h1[(t - 1) & 1];
            }
            __half* outp = (layer == 0) ? (g_hs0 + (size_t)t * BH) : g_h1[t & 1];

            auto load_chunk = [&](int ck) {
                const int buf = ck & 1;
                const int kk = ck * 128;
                const __half* asrc = (kk < H_SZ) ? xs : hs;
                const int koff = kk & (H_SZ - 1);
                #pragma unroll
                for (int i = 0; i < 4; i++) {
                    int idx = tid + i * 512;              // 0..2047
                    int row = idx >> 4, c16 = idx & 15;
                    size_t ga = (size_t)(m0 + row) * H_SZ + koff + c16 * 8;
                    cpasync16(sb + OFF_A(buf) + row * PITCH_A + c16 * 16, asrc + ga);
                }
                CP_COMMIT();
            };

            float acc[2][4][4];
            #pragma unroll
            for (int a = 0; a < 2; a++)
                #pragma unroll
                for (int b = 0; b < 4; b++)
                    #pragma unroll
                    for (int q = 0; q < 4; q++) acc[a][b][q] = 0.f;

            if (!have0) load_chunk(0);
            have0 = false;

            #pragma unroll 1
            for (int ck = 0; ck < 4; ck++) {
                const int buf = ck & 1;
                if (ck < 3) load_chunk(ck + 1);
                if (ck < 3) { CP_WAIT1(); } else { CP_WAIT0(); }
                __syncthreads();

                #pragma unroll
                for (int ks = 0; ks < 8; ks++) {
                    const uint32_t kb = (uint32_t)(ck * 256 + ks * 32);   // B byte col
                    const uint32_t ka = (uint32_t)(ks * 32);               // A byte col
                    uint32_t bf[4][2];
                    #pragma unroll
                    for (int blk = 0; blk < 2; blk++) {
                        uint32_t ad = sb + OFF_BW + (wn * 32 + blk * 16) * PITCH_B + kb + b_lane;
                        LDSM4(bf[blk * 2][0], bf[blk * 2][1],
                              bf[blk * 2 + 1][0], bf[blk * 2 + 1][1], ad);
                    }
                    uint32_t af[2][4];
                    #pragma unroll
                    for (int mf = 0; mf < 2; mf++) {
                        uint32_t ad = sb + OFF_A(buf) + (wm * 32 + mf * 16) * PITCH_A + ka + a_lane;
                        LDSM4(af[mf][0], af[mf][1], af[mf][2], af[mf][3], ad);
                    }
                    #pragma unroll
                    for (int mf = 0; mf < 2; mf++)
                        #pragma unroll
                        for (int nf = 0; nf < 4; nf++)
                            MMA16816(acc[mf][nf], af[mf], bf[nf]);
                }
                __syncthreads();
            }

            // ---- shuffle epilogue (R15-proven) ----
            const bool odd = (lane & 1);
            #pragma unroll
            for (int mf = 0; mf < 2; mf++)
                #pragma unroll
                for (int nf = 0; nf < 4; nf++) {
                    float q0 = acc[mf][nf][0], q1 = acc[mf][nf][1];
                    float q2 = acc[mf][nf][2], q3 = acc[mf][nf][3];
                    float r0 = __shfl_xor_sync(0xFFFFFFFFu, odd ? q0 : q2, 1);
                    float r1 = __shfl_xor_sync(0xFFFFFFFFu, odd ? q1 : q3, 1);
                    float gi = odd ? r0 : q0;
                    float gf = odd ? r1 : q1;
                    float gg = odd ? q2 : r0;
                    float go = odd ? q3 : r1;
                    int jl = wn * 8 + nf * 2 + ((lane & 3) >> 1);             // 0..31
                    int rl = wm * 32 + mf * 16 + (lane >> 2) + (odd ? 8 : 0); // 0..127
                    float4 bq = *(const float4*)(smem + OFF_BIAS + jl * 16);
                    gi += bq.x; gf += bq.y; gg += bq.z; go += bq.w;
                    float cold = c_reg[mf][nf];
                    float cn = fsigm(gf) * cold + fsigm(gi) * ftanh(gg);
                    c_reg[mf][nf] = cn;
                    float hn = fsigm(go) * ftanh(cn);
                    *(__half*)(smem + OFF_HST + rl * PITCH_H + jl * 2) = __float2half(hn);
                }
            __syncthreads();
            // coalesced h store: 512 threads x 16B = 128 rows x 32 fp16
            {
                int row = tid >> 2, c16 = tid & 3;
                int4 v = *(const int4*)(smem + OFF_HST + row * PITCH_H + c16 * 16);
                *(int4*)(outp + (size_t)(m0 + row) * H_SZ + j0 + c16 * 8) = v;
            }
            __threadfence();          // publish h to L2
            __syncthreads();          // all threads' stores fenced
            if (layer == 0 && tid == 0) atomicAdd(&g_hs0done[mblk], 1u);
        }

        // ---- pre-barrier prefetch of next wave's chunk 0 ----
        if (u < T_SZ) {
            const int nt = u + 1 - layer;     // next wave's step for this layer
            if (nt >= 0 && nt < T_SZ) {
                if (layer == 1) {
                    // wait until 8 same-mblk L0 CTAs published hs0[nt] (acyclic)
                    if (tid == 0) {
                        const unsigned tgt = 8u * (unsigned)(nt + 1);
                        while (*(volatile unsigned*)&g_hs0done[mblk] < tgt)
                            __nanosleep(64);
                    }
                    __syncthreads();
                    asm volatile("" ::: "memory");
                }
                prefetch0(nt);                 // buf0 is dead post-epilogue
                have0 = true;
            }

            // ---- global barrier (R15-proven, unchanged) ----
            __threadfence();
            __syncthreads();
            if (tid == 0) {
                unsigned arrived = atomicAdd(&g_cnt, 1);
                if (arrived == NCTA - 1) {
                    g_cnt = 0;
                    __threadfence();
                    g_gen = gen + 1;  // release
                } else {
                    while (g_gen == gen) __nanosleep(64);
                }
            }
            __syncthreads();
            gen++;
        }
    }
}

// ---------------------------------------------------------------------------
// FC head
// ---------------------------------------------------------------------------
__global__ __launch_bounds__(128) void fc_head(const float* __restrict__ fc1w,
                                               const float* __restrict__ fc1b,
                                               const float* __restrict__ fc2w,
                                               const float* __restrict__ fc2b,
                                               float* __restrict__ out) {
    __shared__ float sh[H_SZ];
    __shared__ float red[128];
    const int b = blockIdx.x, t = threadIdx.x;
    const __half* hh = g_h1[(T_SZ - 1) & 1];
    sh[t]       = __half2float(hh[b * H_SZ + t]);
    sh[t + 128] = __half2float(hh[b * H_SZ + t + 128]);
    __syncthreads();
    float acc = 0.f;
    const float* wr = fc1w + t * H_SZ;
    #pragma unroll 8
    for (int k = 0; k < H_SZ; k++) acc += sh[k] * wr[k];
    acc += fc1b[t];
    acc = fmaxf(acc, 0.f) * fc2w[t];
    red[t] = acc;
    __syncthreads();
    for (int s = 64; s > 0; s >>= 1) {
        if (t < s) red[t] += red[t + s];
        __syncthreads();
    }
    if (t == 0) out[b] = 1.f / (1.f + expf(-(red[0] + fc2b[0])));
}

// ---------------------------------------------------------------------------
// Launch
// ---------------------------------------------------------------------------
extern "C" void kernel_launch(void* const* d_in, const int* in_sizes, int n_in,
                              void* d_out, int out_size) {
    const float* x    = (const float*)d_in[0];
    const float* wih0 = (const float*)d_in[1];
    const float* whh0 = (const float*)d_in[2];
    const float* bih0 = (const float*)d_in[3];
    const float* bhh0 = (const float*)d_in[4];
    const float* wih1 = (const float*)d_in[5];
    const float* whh1 = (const float*)d_in[6];
    const float* bih1 = (const float*)d_in[7];
    const float* bhh1 = (const float*)d_in[8];
    const float* fc1w = (const float*)d_in[9];
    const float* fc1b = (const float*)d_in[10];
    const float* fc2w = (const float*)d_in[11];
    const float* fc2b = (const float*)d_in[12];
    float* out = (float*)d_out;

    cudaFuncSetAttribute(lstm_persistent, cudaFuncAttributeMaxDynamicSharedMemorySize, SMEM_TOTAL);

    prep_weights<<<(2 * NG * KC + 255) / 256, 256>>>(wih0, whh0, wih1, whh1);
    prep_bias<<<(2 * NG + 255) / 256, 256>>>(bih0, bhh0, bih1, bhh1);  // also zeros g_hs0done
    relu_cvt<<<(T_SZ * B_SZ * (H_SZ / 4) + 255) / 256, 256>>>(x);

    dim3 grid(NG / 128, B_SZ / 128, 2);   // 128 CTAs, all co-resident
    lstm_persistent<<<grid, 512, SMEM_TOTAL>>>();

    fc_head<<<B_SZ, 128>>>(fc1w, fc1b, fc2w, fc2b, out);
}